// round 4
// baseline (speedup 1.0000x reference)
#include <cuda_runtime.h>

#define W_IMG   1248
#define NROWS   768
#define SPAN    624               // outputs per CTA (2 CTAs per row)
#define HALO    192
#define NT      128               // 4 warps
#define CHUNK   8
#define U_TOT   1024              // NT * CHUNK local elements (halo + span, zero padded)
#define PADIDX(u) ((u) + ((u) >> 3))   // bank-conflict-free padding

__global__ __launch_bounds__(NT) void stereo_halo_kernel(
    const float* __restrict__ L,
    const float* __restrict__ R,
    float* __restrict__ out)
{
    __shared__ float2 PQ[U_TOT + U_TOT / 8];   // global (CTA-wide) inclusive prefix at pad(u)
    __shared__ float2 WT[NT / 32];             // per-warp totals

    const int bid  = blockIdx.x;
    const int row  = bid >> 1;
    const int w0   = (bid & 1) * SPAN;         // 0 or 624
    const int jb   = w0 - HALO;                // global column of local u=0  (-192 or 432)

    const float* __restrict__ r = R + (size_t)row * W_IMG;
    const float* __restrict__ l = L + (size_t)row * W_IMG;
    float* __restrict__ o = out + (size_t)row * W_IMG;

    const int t    = threadIdx.x;
    const int lane = t & 31;
    const int warp = t >> 5;
    const int u0   = t * CHUNK;
    const int j0   = jb + u0;
    // whole 8-chunk validity (both boundaries are multiples of 8)
    const bool vld = (j0 >= 0) && (j0 + CHUNK <= W_IMG);

    // ---- issue all global loads up front (r chunk + l outputs), MLP-heavy ----
    float4 r0, r1;
    if (vld) {
        r0 = *(const float4*)(r + j0);
        r1 = *(const float4*)(r + j0 + 4);
    } else {
        r0 = r1 = make_float4(0.f, 0.f, 0.f, 0.f);
    }
    float lv[5];
    #pragma unroll
    for (int s = 0; s < 5; s++) {
        int u = HALO + t + NT * s;             // output local coord
        lv[s] = (u < HALO + SPAN) ? l[w0 + u - HALO] : 0.f;
    }

    // ---- serial scan of the 8-chunk (local coordinates u) ----
    float rv[8] = {r0.x, r0.y, r0.z, r0.w, r1.x, r1.y, r1.z, r1.w};
    float lp[8], lq[8];
    float p = 0.f, q = 0.f;
    #pragma unroll
    for (int s = 0; s < 8; s++) {
        p += rv[s];
        q = fmaf((float)(u0 + s), rv[s], q);
        lp[s] = p;
        lq[s] = q;
    }

    // ---- inclusive warp scan of thread totals ----
    float vp = p, vq = q;
    #pragma unroll
    for (int off = 1; off < 32; off <<= 1) {
        float ap = __shfl_up_sync(0xffffffffu, vp, off);
        float aq = __shfl_up_sync(0xffffffffu, vq, off);
        if (lane >= off) { vp += ap; vq += aq; }
    }
    if (lane == 31) WT[warp] = make_float2(vp, vq);
    __syncthreads();

    // ---- add cross-warp offset, publish CTA-global inclusive prefix ----
    float offp = vp - p;                       // exclusive within warp
    float offq = vq - q;
    #pragma unroll
    for (int k = 0; k < NT / 32 - 1; k++) {    // warps before mine (uniform per warp)
        if (warp > k) { offp += WT[k].x; offq += WT[k].y; }
    }
    #pragma unroll
    for (int s = 0; s < 8; s++) {
        PQ[PADIDX(u0 + s)] = make_float2(lp[s] + offp, lq[s] + offq);
    }
    __syncthreads();

    // ---- outputs: uniform formula, every window interior to local array ----
    #pragma unroll
    for (int s = 0; s < 5; s++) {
        int u = HALO + t + NT * s;
        if (u < HALO + SPAN) {
            float2 a = PQ[PADIDX(u)];          // inclusive prefix at u
            float2 b = PQ[PADIDX(u - 192)];    // inclusive prefix at u-192
            float S = (float)u * (a.x - b.x) - (a.y - b.y);
            o[w0 + u - HALO] = lv[s] * S;
        }
    }
}

extern "C" void kernel_launch(void* const* d_in, const int* in_sizes, int n_in,
                              void* d_out, int out_size)
{
    const float* left  = (const float*)d_in[0];
    const float* right = (const float*)d_in[1];
    float* out = (float*)d_out;
    stereo_halo_kernel<<<NROWS * 2, NT>>>(left, right, out);
}